// round 6
// baseline (speedup 1.0000x reference)
#include <cuda_runtime.h>
#include <cuda_fp16.h>
#include <cstdint>

#define HIDDEN 128
#define MAX_NODES 50000
#define MAX_EDGES 500000
#define NB 128            // preprocessing grid — all blocks resident (<= SM count)
#define TPB_PRE 256

// Scratch (static __device__ arrays — no allocation allowed).
__device__ uint2 g_feah[MAX_NODES * 32];           // fea as fp16 (4 halfs / uint2)
__device__ uint2 g_learn1h[MAX_NODES * 32];        // learn1 as fp16
__device__ int   g_counts[MAX_NODES];
__device__ int   g_offsets[MAX_NODES + 1];         // padded-CSR offsets (even)
__device__ int   g_rank[MAX_EDGES];
__device__ int   g_bsum[NB];
__device__ __align__(16) int2 g_edges[MAX_EDGES + MAX_NODES];  // padded edges
__device__ unsigned int g_count_bar;               // grid barrier state
__device__ unsigned int g_gen_bar;

// ---------------------------------------------------------------------------
// helpers
// ---------------------------------------------------------------------------
__device__ __forceinline__ uint2 pack4h(float4 a) {
    __half2 h01 = __floats2half2_rn(a.x, a.y);
    __half2 h23 = __floats2half2_rn(a.z, a.w);
    uint2 g;
    g.x = *reinterpret_cast<uint32_t*>(&h01);
    g.y = *reinterpret_cast<uint32_t*>(&h23);
    return g;
}

__device__ __forceinline__ float4 unpack4h(uint2 g) {
    __half2 h01 = *reinterpret_cast<__half2*>(&g.x);
    __half2 h23 = *reinterpret_cast<__half2*>(&g.y);
    float2 f01 = __half22float2(h01);
    float2 f23 = __half22float2(h23);
    return make_float4(f01.x, f01.y, f23.x, f23.y);
}

__device__ __forceinline__ void fma4h(float4& acc, float v, uint2 g) {
    float4 f = unpack4h(g);
    acc.x += v * f.x; acc.y += v * f.y; acc.z += v * f.z; acc.w += v * f.w;
}

// Grid-wide spin barrier (all NB blocks resident by construction).
// Protocol is phase-relative: g_count_bar returns to 0 each barrier, g_gen_bar
// monotonically increases across calls/replays (compared by equality only).
__device__ __forceinline__ void gridsync() {
    __syncthreads();
    if (threadIdx.x == 0) {
        volatile unsigned int* vgen = &g_gen_bar;
        unsigned int gen = *vgen;
        __threadfence();
        if (atomicAdd(&g_count_bar, 1u) == gridDim.x - 1) {
            g_count_bar = 0;
            __threadfence();
            atomicAdd(&g_gen_bar, 1u);     // release
        } else {
            while (*vgen == gen) __nanosleep(64);
        }
        __threadfence();                   // acquire
    }
    __syncthreads();
}

// ---------------------------------------------------------------------------
// Fused preprocessing (single launch):
//  A) zero counts + convert fea->fp16
//  B) histogram + within-row rank
//  C) per-block padded-count block scan -> bsum
//  D) cross-block prefix + write exclusive offsets (row starts even)
//  E) permute edges + write zero-pad edges for odd-degree rows
// ---------------------------------------------------------------------------
__global__ void __launch_bounds__(TPB_PRE)
preprocess_kernel(const float4* __restrict__ fea,
                  const int* __restrict__ row,
                  const int* __restrict__ col,
                  const float* __restrict__ val,
                  int n_nodes, int n_edges, int total4) {
    const int nthreads = gridDim.x * blockDim.x;
    const int gtid = blockIdx.x * blockDim.x + threadIdx.x;
    const int t = threadIdx.x;

    // ---- A: zero counts, convert fea -> fp16 ----
    for (int i = gtid; i < n_nodes; i += nthreads) g_counts[i] = 0;
    for (int i = gtid; i < total4; i += nthreads) g_feah[i] = pack4h(__ldg(fea + i));
    gridsync();

    // ---- B: histogram + rank ----
    for (int e = gtid; e < n_edges; e += nthreads)
        g_rank[e] = atomicAdd(&g_counts[__ldg(row + e)], 1);
    gridsync();

    // ---- C: block-local scan of padded counts ----
    __shared__ int s[TPB_PRE];
    __shared__ int sb[TPB_PRE];     // >= NB
    int rpb = (n_nodes + gridDim.x - 1) / gridDim.x;   // rows per block (<=512)
    int rbeg = blockIdx.x * rpb;
    int rend = min(rbeg + rpb, n_nodes);
    int r0 = rbeg + t * 2;
    int r1 = r0 + 1;
    int c0 = 0, c1 = 0;             // padded (even) counts
    if (r0 < rend) c0 = (g_counts[r0] + 1) & ~1;
    if (r1 < rend) c1 = (g_counts[r1] + 1) & ~1;
    s[t] = c0 + c1;
    __syncthreads();
    for (int off = 1; off < TPB_PRE; off <<= 1) {
        int v = (t >= off) ? s[t - off] : 0;
        __syncthreads();
        s[t] += v;
        __syncthreads();
    }
    if (t == TPB_PRE - 1) g_bsum[blockIdx.x] = s[TPB_PRE - 1];
    gridsync();

    // ---- D: cross-block prefix + write offsets ----
    if (t < NB) sb[t] = g_bsum[t];
    __syncthreads();
    for (int off = 1; off < NB; off <<= 1) {
        int v = (t >= off && t < NB) ? sb[t - off] : 0;
        __syncthreads();
        if (t < NB) sb[t] += v;
        __syncthreads();
    }
    int bpref = (blockIdx.x > 0) ? sb[blockIdx.x - 1] : 0;
    int run = bpref + ((t > 0) ? s[t - 1] : 0);
    if (r0 < rend) { g_offsets[r0] = run; run += c0; }
    if (r1 < rend) { g_offsets[r1] = run; }
    if (blockIdx.x == 0 && t == 0) g_offsets[n_nodes] = sb[NB - 1];
    gridsync();

    // ---- E: permute + pad ----
    for (int e = gtid; e < n_edges; e += nthreads) {
        int r = __ldg(row + e);
        int pos = g_offsets[r] + g_rank[e];
        g_edges[pos] = make_int2(__ldg(col + e), __float_as_int(__ldg(val + e)));
    }
    for (int i = gtid; i < n_nodes; i += nthreads) {
        int c = g_counts[i];
        if (c & 1) g_edges[g_offsets[i] + c] = make_int2(i, 0);  // val=0 pad
    }
}

// ---------------------------------------------------------------------------
// layer 1: learn1h = fp16( spmm_h(fea_h) + bias0 )
// warp per row; edge descs as int4 (2 edges/LDG); fp16 gathers; fp32 acc.
// Row edge ranges are even-length (zero-padded), so every int4 is aligned.
// ---------------------------------------------------------------------------
__global__ void __launch_bounds__(256)
spmm1_kernel(const uint2* __restrict__ xh,
             uint2* __restrict__ yh,
             const int* __restrict__ offsets,
             const int4* __restrict__ edges4,     // aliased g_edges
             const float4* __restrict__ bias4,
             int n_nodes) {
    int gtid = blockIdx.x * blockDim.x + threadIdx.x;
    int r = gtid >> 5;
    if (r >= n_nodes) return;
    int lane = threadIdx.x & 31;

    float4 acc = __ldg(bias4 + lane);
    int beg = __ldg(offsets + r);        // even
    int end = __ldg(offsets + r + 1);    // even

    int i = beg;
    for (; i + 8 <= end; i += 8) {
        int4 d0 = __ldg(edges4 + (i >> 1));
        int4 d1 = __ldg(edges4 + (i >> 1) + 1);
        int4 d2 = __ldg(edges4 + (i >> 1) + 2);
        int4 d3 = __ldg(edges4 + (i >> 1) + 3);
        uint2 g0 = __ldg(xh + (size_t)d0.x * 32 + lane);
        uint2 g1 = __ldg(xh + (size_t)d0.z * 32 + lane);
        uint2 g2 = __ldg(xh + (size_t)d1.x * 32 + lane);
        uint2 g3 = __ldg(xh + (size_t)d1.z * 32 + lane);
        uint2 g4 = __ldg(xh + (size_t)d2.x * 32 + lane);
        uint2 g5 = __ldg(xh + (size_t)d2.z * 32 + lane);
        uint2 g6 = __ldg(xh + (size_t)d3.x * 32 + lane);
        uint2 g7 = __ldg(xh + (size_t)d3.z * 32 + lane);
        fma4h(acc, __int_as_float(d0.y), g0);
        fma4h(acc, __int_as_float(d0.w), g1);
        fma4h(acc, __int_as_float(d1.y), g2);
        fma4h(acc, __int_as_float(d1.w), g3);
        fma4h(acc, __int_as_float(d2.y), g4);
        fma4h(acc, __int_as_float(d2.w), g5);
        fma4h(acc, __int_as_float(d3.y), g6);
        fma4h(acc, __int_as_float(d3.w), g7);
    }
    int m = end - i;                      // 0, 2, 4, or 6
    if (m > 0) {
        int4 d0, d1, d2;
        uint2 g0, g1, g2, g3, g4, g5;
        d0 = __ldg(edges4 + (i >> 1));
        if (m > 2) d1 = __ldg(edges4 + (i >> 1) + 1);
        if (m > 4) d2 = __ldg(edges4 + (i >> 1) + 2);
        g0 = __ldg(xh + (size_t)d0.x * 32 + lane);
        g1 = __ldg(xh + (size_t)d0.z * 32 + lane);
        if (m > 2) { g2 = __ldg(xh + (size_t)d1.x * 32 + lane);
                     g3 = __ldg(xh + (size_t)d1.z * 32 + lane); }
        if (m > 4) { g4 = __ldg(xh + (size_t)d2.x * 32 + lane);
                     g5 = __ldg(xh + (size_t)d2.z * 32 + lane); }
        fma4h(acc, __int_as_float(d0.y), g0);
        fma4h(acc, __int_as_float(d0.w), g1);
        if (m > 2) { fma4h(acc, __int_as_float(d1.y), g2);
                     fma4h(acc, __int_as_float(d1.w), g3); }
        if (m > 4) { fma4h(acc, __int_as_float(d2.y), g4);
                     fma4h(acc, __int_as_float(d2.w), g5); }
    }

    yh[(size_t)r * 32 + lane] = pack4h(acc);
}

// ---------------------------------------------------------------------------
// layer 2 + fused final: out = (fea + learn1h + spmm_h(learn1h) + bias1) / 3
// ---------------------------------------------------------------------------
__global__ void __launch_bounds__(256)
spmm2_kernel(const uint2* __restrict__ xh,       // learn1 fp16
             const float4* __restrict__ fea,
             float4* __restrict__ out,
             const int* __restrict__ offsets,
             const int4* __restrict__ edges4,
             const float4* __restrict__ bias4,
             int n_nodes) {
    int gtid = blockIdx.x * blockDim.x + threadIdx.x;
    int r = gtid >> 5;
    if (r >= n_nodes) return;
    int lane = threadIdx.x & 31;

    float4 acc = __ldg(bias4 + lane);
    int beg = __ldg(offsets + r);
    int end = __ldg(offsets + r + 1);

    int i = beg;
    for (; i + 8 <= end; i += 8) {
        int4 d0 = __ldg(edges4 + (i >> 1));
        int4 d1 = __ldg(edges4 + (i >> 1) + 1);
        int4 d2 = __ldg(edges4 + (i >> 1) + 2);
        int4 d3 = __ldg(edges4 + (i >> 1) + 3);
        uint2 g0 = __ldg(xh + (size_t)d0.x * 32 + lane);
        uint2 g1 = __ldg(xh + (size_t)d0.z * 32 + lane);
        uint2 g2 = __ldg(xh + (size_t)d1.x * 32 + lane);
        uint2 g3 = __ldg(xh + (size_t)d1.z * 32 + lane);
        uint2 g4 = __ldg(xh + (size_t)d2.x * 32 + lane);
        uint2 g5 = __ldg(xh + (size_t)d2.z * 32 + lane);
        uint2 g6 = __ldg(xh + (size_t)d3.x * 32 + lane);
        uint2 g7 = __ldg(xh + (size_t)d3.z * 32 + lane);
        fma4h(acc, __int_as_float(d0.y), g0);
        fma4h(acc, __int_as_float(d0.w), g1);
        fma4h(acc, __int_as_float(d1.y), g2);
        fma4h(acc, __int_as_float(d1.w), g3);
        fma4h(acc, __int_as_float(d2.y), g4);
        fma4h(acc, __int_as_float(d2.w), g5);
        fma4h(acc, __int_as_float(d3.y), g6);
        fma4h(acc, __int_as_float(d3.w), g7);
    }
    int m = end - i;
    if (m > 0) {
        int4 d0, d1, d2;
        uint2 g0, g1, g2, g3, g4, g5;
        d0 = __ldg(edges4 + (i >> 1));
        if (m > 2) d1 = __ldg(edges4 + (i >> 1) + 1);
        if (m > 4) d2 = __ldg(edges4 + (i >> 1) + 2);
        g0 = __ldg(xh + (size_t)d0.x * 32 + lane);
        g1 = __ldg(xh + (size_t)d0.z * 32 + lane);
        if (m > 2) { g2 = __ldg(xh + (size_t)d1.x * 32 + lane);
                     g3 = __ldg(xh + (size_t)d1.z * 32 + lane); }
        if (m > 4) { g4 = __ldg(xh + (size_t)d2.x * 32 + lane);
                     g5 = __ldg(xh + (size_t)d2.z * 32 + lane); }
        fma4h(acc, __int_as_float(d0.y), g0);
        fma4h(acc, __int_as_float(d0.w), g1);
        if (m > 2) { fma4h(acc, __int_as_float(d1.y), g2);
                     fma4h(acc, __int_as_float(d1.w), g3); }
        if (m > 4) { fma4h(acc, __int_as_float(d2.y), g4);
                     fma4h(acc, __int_as_float(d2.w), g5); }
    }

    size_t idx = (size_t)r * 32 + lane;
    const float inv3 = 1.0f / 3.0f;
    float4 f  = __ldg(fea + idx);
    float4 l1 = unpack4h(__ldg(xh + idx));     // fp16 residual
    acc.x = (f.x + l1.x + acc.x) * inv3;
    acc.y = (f.y + l1.y + acc.y) * inv3;
    acc.z = (f.z + l1.z + acc.z) * inv3;
    acc.w = (f.w + l1.w + acc.w) * inv3;
    out[idx] = acc;
}

extern "C" void kernel_launch(void* const* d_in, const int* in_sizes, int n_in,
                              void* d_out, int out_size) {
    const float* fea     = (const float*)d_in[0];
    const int*   adj_row = (const int*)  d_in[1];
    const int*   adj_col = (const int*)  d_in[2];
    const float* adj_val = (const float*)d_in[3];
    const float* bias    = (const float*)d_in[4];

    int n_edges = in_sizes[1];
    int n_nodes = in_sizes[0] / HIDDEN;
    int total4  = n_nodes * 32;

    uint2* feah;    cudaGetSymbolAddress((void**)&feah,    g_feah);
    uint2* learn1h; cudaGetSymbolAddress((void**)&learn1h, g_learn1h);
    int*   offs;    cudaGetSymbolAddress((void**)&offs,    g_offsets);
    int2*  edges;   cudaGetSymbolAddress((void**)&edges,   g_edges);
    float* out = (float*)d_out;

    // 1) fused preprocessing (sort into padded CSR + fp16 convert)
    preprocess_kernel<<<NB, TPB_PRE>>>((const float4*)fea, adj_row, adj_col,
                                       adj_val, n_nodes, n_edges, total4);

    // 2) layer 1
    {
        int blocks = (n_nodes * 32 + 255) / 256;
        spmm1_kernel<<<blocks, 256>>>(feah, learn1h, offs, (const int4*)edges,
                                      (const float4*)bias, n_nodes);
    }

    // 3) layer 2 + fused final
    {
        int blocks = (n_nodes * 32 + 255) / 256;
        spmm2_kernel<<<blocks, 256>>>(learn1h, (const float4*)fea, (float4*)out,
                                      offs, (const int4*)edges,
                                      (const float4*)(bias + HIDDEN), n_nodes);
    }
}

// round 7
// speedup vs baseline: 1.3880x; 1.3880x over previous
#include <cuda_runtime.h>
#include <cuda_fp16.h>
#include <cstdint>

#define HIDDEN 128
#define MAX_NODES 50000
#define MAX_EDGES 500000
#define SCAN_CHUNK 1024
#define MAX_SBLOCKS ((MAX_NODES + SCAN_CHUNK - 1) / SCAN_CHUNK)   // 49

// Scratch (static __device__ arrays — no allocation allowed).
__device__ uint2 g_feah[MAX_NODES * 32];           // fea as fp16 (4 halfs / uint2)
__device__ uint2 g_learn1h[MAX_NODES * 32];        // learn1 as fp16
__device__ int   g_counts[MAX_NODES];
__device__ int   g_offsets[MAX_NODES + 1];         // padded-CSR offsets (even)
__device__ int   g_rank[MAX_EDGES];
__device__ int   g_bsum[MAX_SBLOCKS];
__device__ __align__(16) int2 g_edges[MAX_EDGES + MAX_NODES];   // padded edges

// ---------------------------------------------------------------------------
// helpers
// ---------------------------------------------------------------------------
__device__ __forceinline__ uint2 pack4h(float4 a) {
    __half2 h01 = __floats2half2_rn(a.x, a.y);
    __half2 h23 = __floats2half2_rn(a.z, a.w);
    uint2 g;
    g.x = *reinterpret_cast<uint32_t*>(&h01);
    g.y = *reinterpret_cast<uint32_t*>(&h23);
    return g;
}

__device__ __forceinline__ float4 unpack4h(uint2 g) {
    __half2 h01 = *reinterpret_cast<__half2*>(&g.x);
    __half2 h23 = *reinterpret_cast<__half2*>(&g.y);
    float2 f01 = __half22float2(h01);
    float2 f23 = __half22float2(h23);
    return make_float4(f01.x, f01.y, f23.x, f23.y);
}

__device__ __forceinline__ void fma4h(float4& acc, float v, uint2 g) {
    float4 f = unpack4h(g);
    acc.x += v * f.x; acc.y += v * f.y; acc.z += v * f.z; acc.w += v * f.w;
}

// ---------------------------------------------------------------------------
// 1) prep: convert fea -> fp16 shadow, zero counts  (full-width grid)
// ---------------------------------------------------------------------------
__global__ void prep_kernel(const float4* __restrict__ fea,
                            uint2* __restrict__ feah,
                            int* __restrict__ counts,
                            int n_nodes, int total4) {
    int i = blockIdx.x * blockDim.x + threadIdx.x;
    if (i < total4) feah[i] = pack4h(__ldg(fea + i));
    if (i < n_nodes) counts[i] = 0;
}

// ---------------------------------------------------------------------------
// 2) fused histogram + within-row rank
// ---------------------------------------------------------------------------
__global__ void hist_rank_kernel(const int* __restrict__ row,
                                 int* __restrict__ counts,
                                 int* __restrict__ rank, int n_edges) {
    int e = blockIdx.x * blockDim.x + threadIdx.x;
    if (e < n_edges) rank[e] = atomicAdd(&counts[__ldg(row + e)], 1);
}

// ---------------------------------------------------------------------------
// 3a) per-1024-chunk block sums of PADDED counts ((c+1)&~1)
// ---------------------------------------------------------------------------
__global__ void scan_bsum_kernel(const int* __restrict__ counts,
                                 int* __restrict__ bsum, int n) {
    __shared__ int s[256];
    int t = threadIdx.x;
    int base = blockIdx.x * SCAN_CHUNK + t * 4;
    int sum = 0;
    #pragma unroll
    for (int k = 0; k < 4; k++)
        if (base + k < n) sum += (__ldg(counts + base + k) + 1) & ~1;
    s[t] = sum;
    __syncthreads();
    for (int off = 1; off < 256; off <<= 1) {
        int v = (t >= off) ? s[t - off] : 0;
        __syncthreads();
        s[t] += v;
        __syncthreads();
    }
    if (t == 255) bsum[blockIdx.x] = s[255];
}

// ---------------------------------------------------------------------------
// 3b) final scan: parallel smem scan of bsum, then block-local scan of
//     padded counts -> exclusive offsets (every row start is even).
// ---------------------------------------------------------------------------
__global__ void scan_offsets_kernel(const int* __restrict__ counts,
                                    const int* __restrict__ bsum,
                                    int* __restrict__ offsets,
                                    int n, int nblocks) {
    __shared__ int s[256];
    __shared__ int sb[64];
    int t = threadIdx.x;
    int b = blockIdx.x;

    if (t < 64) sb[t] = (t < nblocks) ? __ldg(bsum + t) : 0;
    __syncthreads();
    for (int off = 1; off < 64; off <<= 1) {
        int v = (t >= off && t < 64) ? sb[t - off] : 0;
        __syncthreads();
        if (t < 64) sb[t] += v;
        __syncthreads();
    }
    int bpref = (b > 0) ? sb[b - 1] : 0;

    int base = b * SCAN_CHUNK + t * 4;
    int c0 = (base + 0 < n) ? ((__ldg(counts + base + 0) + 1) & ~1) : 0;
    int c1 = (base + 1 < n) ? ((__ldg(counts + base + 1) + 1) & ~1) : 0;
    int c2 = (base + 2 < n) ? ((__ldg(counts + base + 2) + 1) & ~1) : 0;
    int c3 = (base + 3 < n) ? ((__ldg(counts + base + 3) + 1) & ~1) : 0;
    s[t] = c0 + c1 + c2 + c3;
    __syncthreads();
    for (int off = 1; off < 256; off <<= 1) {
        int v = (t >= off) ? s[t - off] : 0;
        __syncthreads();
        s[t] += v;
        __syncthreads();
    }

    int run = bpref + ((t > 0) ? s[t - 1] : 0);
    if (base + 0 < n) offsets[base + 0] = run; run += c0;
    if (base + 1 < n) offsets[base + 1] = run; run += c1;
    if (base + 2 < n) offsets[base + 2] = run; run += c2;
    if (base + 3 < n) offsets[base + 3] = run;

    if (b == 0 && t == 0) offsets[n] = sb[nblocks - 1];   // padded total
}

// ---------------------------------------------------------------------------
// 4) permute edges (no atomics) + write zero-pad edge for odd-degree rows
// ---------------------------------------------------------------------------
__global__ void permute_pad_kernel(const int* __restrict__ row,
                                   const int* __restrict__ col,
                                   const float* __restrict__ val,
                                   const int* __restrict__ rank,
                                   const int* __restrict__ offsets,
                                   const int* __restrict__ counts,
                                   int2* __restrict__ edges,
                                   int n_edges, int n_nodes) {
    int i = blockIdx.x * blockDim.x + threadIdx.x;
    if (i < n_edges) {
        int r = __ldg(row + i);
        int pos = __ldg(offsets + r) + __ldg(rank + i);
        edges[pos] = make_int2(__ldg(col + i), __float_as_int(__ldg(val + i)));
    }
    if (i < n_nodes) {
        int c = __ldg(counts + i);
        if (c & 1) edges[__ldg(offsets + i) + c] = make_int2(i, 0);  // val=0 pad
    }
}

// ---------------------------------------------------------------------------
// 5) layer 1: learn1h = fp16( spmm_h(fea_h) + bias0 )
//    warp/row; int4 edge descs (2 edges/LDG); fp16 gathers; fp32 accumulate.
// ---------------------------------------------------------------------------
__global__ void __launch_bounds__(256)
spmm1_kernel(const uint2* __restrict__ xh,
             uint2* __restrict__ yh,
             const int* __restrict__ offsets,
             const int4* __restrict__ edges4,
             const float4* __restrict__ bias4,
             int n_nodes) {
    int gtid = blockIdx.x * blockDim.x + threadIdx.x;
    int r = gtid >> 5;
    if (r >= n_nodes) return;
    int lane = threadIdx.x & 31;

    float4 acc = __ldg(bias4 + lane);
    int beg = __ldg(offsets + r);        // even
    int end = __ldg(offsets + r + 1);    // even

    int i = beg;
    for (; i + 8 <= end; i += 8) {
        int4 d0 = __ldg(edges4 + (i >> 1));
        int4 d1 = __ldg(edges4 + (i >> 1) + 1);
        int4 d2 = __ldg(edges4 + (i >> 1) + 2);
        int4 d3 = __ldg(edges4 + (i >> 1) + 3);
        uint2 g0 = __ldg(xh + (size_t)d0.x * 32 + lane);
        uint2 g1 = __ldg(xh + (size_t)d0.z * 32 + lane);
        uint2 g2 = __ldg(xh + (size_t)d1.x * 32 + lane);
        uint2 g3 = __ldg(xh + (size_t)d1.z * 32 + lane);
        uint2 g4 = __ldg(xh + (size_t)d2.x * 32 + lane);
        uint2 g5 = __ldg(xh + (size_t)d2.z * 32 + lane);
        uint2 g6 = __ldg(xh + (size_t)d3.x * 32 + lane);
        uint2 g7 = __ldg(xh + (size_t)d3.z * 32 + lane);
        fma4h(acc, __int_as_float(d0.y), g0);
        fma4h(acc, __int_as_float(d0.w), g1);
        fma4h(acc, __int_as_float(d1.y), g2);
        fma4h(acc, __int_as_float(d1.w), g3);
        fma4h(acc, __int_as_float(d2.y), g4);
        fma4h(acc, __int_as_float(d2.w), g5);
        fma4h(acc, __int_as_float(d3.y), g6);
        fma4h(acc, __int_as_float(d3.w), g7);
    }
    int m = end - i;                      // 0, 2, 4, or 6
    if (m > 0) {
        int4 d0, d1, d2;
        uint2 g0, g1, g2, g3, g4, g5;
        d0 = __ldg(edges4 + (i >> 1));
        if (m > 2) d1 = __ldg(edges4 + (i >> 1) + 1);
        if (m > 4) d2 = __ldg(edges4 + (i >> 1) + 2);
        g0 = __ldg(xh + (size_t)d0.x * 32 + lane);
        g1 = __ldg(xh + (size_t)d0.z * 32 + lane);
        if (m > 2) { g2 = __ldg(xh + (size_t)d1.x * 32 + lane);
                     g3 = __ldg(xh + (size_t)d1.z * 32 + lane); }
        if (m > 4) { g4 = __ldg(xh + (size_t)d2.x * 32 + lane);
                     g5 = __ldg(xh + (size_t)d2.z * 32 + lane); }
        fma4h(acc, __int_as_float(d0.y), g0);
        fma4h(acc, __int_as_float(d0.w), g1);
        if (m > 2) { fma4h(acc, __int_as_float(d1.y), g2);
                     fma4h(acc, __int_as_float(d1.w), g3); }
        if (m > 4) { fma4h(acc, __int_as_float(d2.y), g4);
                     fma4h(acc, __int_as_float(d2.w), g5); }
    }

    yh[(size_t)r * 32 + lane] = pack4h(acc);
}

// ---------------------------------------------------------------------------
// 6) layer 2 + fused final: out = (fea + learn1h + spmm_h(learn1h) + bias1)/3
// ---------------------------------------------------------------------------
__global__ void __launch_bounds__(256)
spmm2_kernel(const uint2* __restrict__ xh,       // learn1 fp16
             const float4* __restrict__ fea,
             float4* __restrict__ out,
             const int* __restrict__ offsets,
             const int4* __restrict__ edges4,
             const float4* __restrict__ bias4,
             int n_nodes) {
    int gtid = blockIdx.x * blockDim.x + threadIdx.x;
    int r = gtid >> 5;
    if (r >= n_nodes) return;
    int lane = threadIdx.x & 31;

    float4 acc = __ldg(bias4 + lane);
    int beg = __ldg(offsets + r);
    int end = __ldg(offsets + r + 1);

    int i = beg;
    for (; i + 8 <= end; i += 8) {
        int4 d0 = __ldg(edges4 + (i >> 1));
        int4 d1 = __ldg(edges4 + (i >> 1) + 1);
        int4 d2 = __ldg(edges4 + (i >> 1) + 2);
        int4 d3 = __ldg(edges4 + (i >> 1) + 3);
        uint2 g0 = __ldg(xh + (size_t)d0.x * 32 + lane);
        uint2 g1 = __ldg(xh + (size_t)d0.z * 32 + lane);
        uint2 g2 = __ldg(xh + (size_t)d1.x * 32 + lane);
        uint2 g3 = __ldg(xh + (size_t)d1.z * 32 + lane);
        uint2 g4 = __ldg(xh + (size_t)d2.x * 32 + lane);
        uint2 g5 = __ldg(xh + (size_t)d2.z * 32 + lane);
        uint2 g6 = __ldg(xh + (size_t)d3.x * 32 + lane);
        uint2 g7 = __ldg(xh + (size_t)d3.z * 32 + lane);
        fma4h(acc, __int_as_float(d0.y), g0);
        fma4h(acc, __int_as_float(d0.w), g1);
        fma4h(acc, __int_as_float(d1.y), g2);
        fma4h(acc, __int_as_float(d1.w), g3);
        fma4h(acc, __int_as_float(d2.y), g4);
        fma4h(acc, __int_as_float(d2.w), g5);
        fma4h(acc, __int_as_float(d3.y), g6);
        fma4h(acc, __int_as_float(d3.w), g7);
    }
    int m = end - i;
    if (m > 0) {
        int4 d0, d1, d2;
        uint2 g0, g1, g2, g3, g4, g5;
        d0 = __ldg(edges4 + (i >> 1));
        if (m > 2) d1 = __ldg(edges4 + (i >> 1) + 1);
        if (m > 4) d2 = __ldg(edges4 + (i >> 1) + 2);
        g0 = __ldg(xh + (size_t)d0.x * 32 + lane);
        g1 = __ldg(xh + (size_t)d0.z * 32 + lane);
        if (m > 2) { g2 = __ldg(xh + (size_t)d1.x * 32 + lane);
                     g3 = __ldg(xh + (size_t)d1.z * 32 + lane); }
        if (m > 4) { g4 = __ldg(xh + (size_t)d2.x * 32 + lane);
                     g5 = __ldg(xh + (size_t)d2.z * 32 + lane); }
        fma4h(acc, __int_as_float(d0.y), g0);
        fma4h(acc, __int_as_float(d0.w), g1);
        if (m > 2) { fma4h(acc, __int_as_float(d1.y), g2);
                     fma4h(acc, __int_as_float(d1.w), g3); }
        if (m > 4) { fma4h(acc, __int_as_float(d2.y), g4);
                     fma4h(acc, __int_as_float(d2.w), g5); }
    }

    size_t idx = (size_t)r * 32 + lane;
    const float inv3 = 1.0f / 3.0f;
    float4 f  = __ldg(fea + idx);
    float4 l1 = unpack4h(__ldg(xh + idx));     // fp16 residual
    acc.x = (f.x + l1.x + acc.x) * inv3;
    acc.y = (f.y + l1.y + acc.y) * inv3;
    acc.z = (f.z + l1.z + acc.z) * inv3;
    acc.w = (f.w + l1.w + acc.w) * inv3;
    out[idx] = acc;
}

extern "C" void kernel_launch(void* const* d_in, const int* in_sizes, int n_in,
                              void* d_out, int out_size) {
    const float* fea     = (const float*)d_in[0];
    const int*   adj_row = (const int*)  d_in[1];
    const int*   adj_col = (const int*)  d_in[2];
    const float* adj_val = (const float*)d_in[3];
    const float* bias    = (const float*)d_in[4];

    int n_edges = in_sizes[1];
    int n_nodes = in_sizes[0] / HIDDEN;
    int total4  = n_nodes * 32;
    int nblocks_scan = (n_nodes + SCAN_CHUNK - 1) / SCAN_CHUNK;

    uint2* feah;    cudaGetSymbolAddress((void**)&feah,    g_feah);
    uint2* learn1h; cudaGetSymbolAddress((void**)&learn1h, g_learn1h);
    int*   counts;  cudaGetSymbolAddress((void**)&counts,  g_counts);
    int*   offs;    cudaGetSymbolAddress((void**)&offs,    g_offsets);
    int*   rank;    cudaGetSymbolAddress((void**)&rank,    g_rank);
    int*   bsum;    cudaGetSymbolAddress((void**)&bsum,    g_bsum);
    int2*  edges;   cudaGetSymbolAddress((void**)&edges,   g_edges);
    float* out = (float*)d_out;

    const int TPB = 256;

    // 1) convert fea -> fp16, zero counts
    prep_kernel<<<(total4 + TPB - 1) / TPB, TPB>>>((const float4*)fea, feah,
                                                   counts, n_nodes, total4);

    // 2) histogram + rank
    hist_rank_kernel<<<(n_edges + TPB - 1) / TPB, TPB>>>(adj_row, counts, rank, n_edges);

    // 3) parallel two-pass scan of PADDED counts -> offsets
    scan_bsum_kernel<<<nblocks_scan, 256>>>(counts, bsum, n_nodes);
    scan_offsets_kernel<<<nblocks_scan, 256>>>(counts, bsum, offs, n_nodes, nblocks_scan);

    // 4) permute + pad (no atomics)
    {
        int work = max(n_edges, n_nodes);
        permute_pad_kernel<<<(work + TPB - 1) / TPB, TPB>>>(
            adj_row, adj_col, adj_val, rank, offs, counts, edges,
            n_edges, n_nodes);
    }

    // 5) layer 1
    {
        int blocks = (n_nodes * 32 + 255) / 256;
        spmm1_kernel<<<blocks, 256>>>(feah, learn1h, offs, (const int4*)edges,
                                      (const float4*)bias, n_nodes);
    }

    // 6) layer 2 + fused final
    {
        int blocks = (n_nodes * 32 + 255) / 256;
        spmm2_kernel<<<blocks, 256>>>(learn1h, (const float4*)fea, (float4*)out,
                                      offs, (const int4*)edges,
                                      (const float4*)(bias + HIDDEN), n_nodes);
    }
}

// round 8
// speedup vs baseline: 1.4941x; 1.0764x over previous
#include <cuda_runtime.h>
#include <cuda_fp16.h>
#include <cstdint>

#define HIDDEN 128
#define MAX_NODES 50000
#define MAX_EDGES 500000
#define SCAN_CHUNK 256
#define MAX_SBLOCKS ((MAX_NODES + SCAN_CHUNK - 1) / SCAN_CHUNK)   // 196

// Scratch (static __device__ arrays — zero-initialized at load; no allocation).
__device__ uint2 g_feah[MAX_NODES * 32];           // fea as fp16 (4 halfs / uint2)
__device__ uint2 g_learn1h[MAX_NODES * 32];        // learn1 as fp16
__device__ int   g_counts[MAX_NODES];              // INVARIANT: zero at call entry
__device__ int   g_offsets[MAX_NODES + 1];         // padded-CSR offsets (even)
__device__ int   g_rank[MAX_EDGES];
__device__ int   g_bsum[MAX_SBLOCKS];
__device__ __align__(16) int2 g_edges[MAX_EDGES + MAX_NODES];   // padded edges

// ---------------------------------------------------------------------------
// helpers
// ---------------------------------------------------------------------------
__device__ __forceinline__ uint2 pack4h(float4 a) {
    __half2 h01 = __floats2half2_rn(a.x, a.y);
    __half2 h23 = __floats2half2_rn(a.z, a.w);
    uint2 g;
    g.x = *reinterpret_cast<uint32_t*>(&h01);
    g.y = *reinterpret_cast<uint32_t*>(&h23);
    return g;
}

__device__ __forceinline__ float4 unpack4h(uint2 g) {
    __half2 h01 = *reinterpret_cast<__half2*>(&g.x);
    __half2 h23 = *reinterpret_cast<__half2*>(&g.y);
    float2 f01 = __half22float2(h01);
    float2 f23 = __half22float2(h23);
    return make_float4(f01.x, f01.y, f23.x, f23.y);
}

__device__ __forceinline__ void fma4h(float4& acc, float v, uint2 g) {
    float4 f = unpack4h(g);
    acc.x += v * f.x; acc.y += v * f.y; acc.z += v * f.z; acc.w += v * f.w;
}

// ---------------------------------------------------------------------------
// 1) fused: fea->fp16 convert  +  histogram/rank (counts pre-zeroed invariant)
//    Independent work items share one grid.
// ---------------------------------------------------------------------------
__global__ void convert_hist_kernel(const float4* __restrict__ fea,
                                    uint2* __restrict__ feah,
                                    const int* __restrict__ row,
                                    int* __restrict__ counts,
                                    int* __restrict__ rank,
                                    int n_edges, int total4) {
    int i = blockIdx.x * blockDim.x + threadIdx.x;
    if (i < total4) feah[i] = pack4h(__ldg(fea + i));
    if (i < n_edges) rank[i] = atomicAdd(&counts[__ldg(row + i)], 1);
}

// ---------------------------------------------------------------------------
// 2) per-256-chunk block sums of PADDED counts ((c+1)&~1) — 196 blocks
// ---------------------------------------------------------------------------
__global__ void scan_bsum_kernel(const int* __restrict__ counts,
                                 int* __restrict__ bsum, int n) {
    __shared__ int s[SCAN_CHUNK];
    int t = threadIdx.x;
    int i = blockIdx.x * SCAN_CHUNK + t;
    s[t] = (i < n) ? ((__ldg(counts + i) + 1) & ~1) : 0;
    __syncthreads();
    for (int off = 1; off < SCAN_CHUNK; off <<= 1) {
        int v = (t >= off) ? s[t - off] : 0;
        __syncthreads();
        s[t] += v;
        __syncthreads();
    }
    if (t == SCAN_CHUNK - 1) bsum[blockIdx.x] = s[SCAN_CHUNK - 1];
}

// ---------------------------------------------------------------------------
// 3) final scan: parallel smem scan of 196 bsums, block-local scan of padded
//    counts -> exclusive offsets; ALSO writes the zero-pad edge for
//    odd-degree rows (offset & count both known here).
// ---------------------------------------------------------------------------
__global__ void scan_offsets_pad_kernel(const int* __restrict__ counts,
                                        const int* __restrict__ bsum,
                                        int* __restrict__ offsets,
                                        int2* __restrict__ edges,
                                        int n, int nblocks) {
    __shared__ int s[SCAN_CHUNK];
    __shared__ int sb[SCAN_CHUNK];
    int t = threadIdx.x;
    int b = blockIdx.x;

    sb[t] = (t < nblocks) ? __ldg(bsum + t) : 0;
    __syncthreads();
    for (int off = 1; off < SCAN_CHUNK; off <<= 1) {
        int v = (t >= off) ? sb[t - off] : 0;
        __syncthreads();
        sb[t] += v;
        __syncthreads();
    }
    int bpref = (b > 0) ? sb[b - 1] : 0;

    int i = b * SCAN_CHUNK + t;
    int c  = (i < n) ? __ldg(counts + i) : 0;
    int cp = (c + 1) & ~1;                     // padded count
    s[t] = cp;
    __syncthreads();
    for (int off = 1; off < SCAN_CHUNK; off <<= 1) {
        int v = (t >= off) ? s[t - off] : 0;
        __syncthreads();
        s[t] += v;
        __syncthreads();
    }

    int run = bpref + ((t > 0) ? s[t - 1] : 0);   // exclusive offset (even)
    if (i < n) {
        offsets[i] = run;
        if (c & 1) edges[run + c] = make_int2(i, 0);   // val=0 pad edge
    }
    if (b == 0 && t == 0) offsets[n] = sb[nblocks - 1];
}

// ---------------------------------------------------------------------------
// 4) permute edges — no atomics: pos = offsets[row] + rank
// ---------------------------------------------------------------------------
__global__ void permute_kernel(const int* __restrict__ row,
                               const int* __restrict__ col,
                               const float* __restrict__ val,
                               const int* __restrict__ rank,
                               const int* __restrict__ offsets,
                               int2* __restrict__ edges, int n_edges) {
    int e = blockIdx.x * blockDim.x + threadIdx.x;
    if (e >= n_edges) return;
    int r = __ldg(row + e);
    int pos = __ldg(offsets + r) + __ldg(rank + e);
    edges[pos] = make_int2(__ldg(col + e), __float_as_int(__ldg(val + e)));
}

// ---------------------------------------------------------------------------
// 5) layer 1: learn1h = fp16( spmm_h(fea_h) + bias0 );
//    also restores counts==0 invariant for the next kernel_launch call.
// ---------------------------------------------------------------------------
__global__ void __launch_bounds__(256)
spmm1_kernel(const uint2* __restrict__ xh,
             uint2* __restrict__ yh,
             const int* __restrict__ offsets,
             const int4* __restrict__ edges4,
             const float4* __restrict__ bias4,
             int* __restrict__ counts,
             int n_nodes) {
    int gtid = blockIdx.x * blockDim.x + threadIdx.x;
    if (gtid < n_nodes) counts[gtid] = 0;      // restore invariant (counts dead now)
    int r = gtid >> 5;
    if (r >= n_nodes) return;
    int lane = threadIdx.x & 31;

    float4 acc = __ldg(bias4 + lane);
    int beg = __ldg(offsets + r);        // even
    int end = __ldg(offsets + r + 1);    // even

    int i = beg;
    for (; i + 8 <= end; i += 8) {
        int4 d0 = __ldg(edges4 + (i >> 1));
        int4 d1 = __ldg(edges4 + (i >> 1) + 1);
        int4 d2 = __ldg(edges4 + (i >> 1) + 2);
        int4 d3 = __ldg(edges4 + (i >> 1) + 3);
        uint2 g0 = __ldg(xh + (size_t)d0.x * 32 + lane);
        uint2 g1 = __ldg(xh + (size_t)d0.z * 32 + lane);
        uint2 g2 = __ldg(xh + (size_t)d1.x * 32 + lane);
        uint2 g3 = __ldg(xh + (size_t)d1.z * 32 + lane);
        uint2 g4 = __ldg(xh + (size_t)d2.x * 32 + lane);
        uint2 g5 = __ldg(xh + (size_t)d2.z * 32 + lane);
        uint2 g6 = __ldg(xh + (size_t)d3.x * 32 + lane);
        uint2 g7 = __ldg(xh + (size_t)d3.z * 32 + lane);
        fma4h(acc, __int_as_float(d0.y), g0);
        fma4h(acc, __int_as_float(d0.w), g1);
        fma4h(acc, __int_as_float(d1.y), g2);
        fma4h(acc, __int_as_float(d1.w), g3);
        fma4h(acc, __int_as_float(d2.y), g4);
        fma4h(acc, __int_as_float(d2.w), g5);
        fma4h(acc, __int_as_float(d3.y), g6);
        fma4h(acc, __int_as_float(d3.w), g7);
    }
    int m = end - i;                      // 0, 2, 4, or 6
    if (m > 0) {
        int4 d0, d1, d2;
        uint2 g0, g1, g2, g3, g4, g5;
        d0 = __ldg(edges4 + (i >> 1));
        if (m > 2) d1 = __ldg(edges4 + (i >> 1) + 1);
        if (m > 4) d2 = __ldg(edges4 + (i >> 1) + 2);
        g0 = __ldg(xh + (size_t)d0.x * 32 + lane);
        g1 = __ldg(xh + (size_t)d0.z * 32 + lane);
        if (m > 2) { g2 = __ldg(xh + (size_t)d1.x * 32 + lane);
                     g3 = __ldg(xh + (size_t)d1.z * 32 + lane); }
        if (m > 4) { g4 = __ldg(xh + (size_t)d2.x * 32 + lane);
                     g5 = __ldg(xh + (size_t)d2.z * 32 + lane); }
        fma4h(acc, __int_as_float(d0.y), g0);
        fma4h(acc, __int_as_float(d0.w), g1);
        if (m > 2) { fma4h(acc, __int_as_float(d1.y), g2);
                     fma4h(acc, __int_as_float(d1.w), g3); }
        if (m > 4) { fma4h(acc, __int_as_float(d2.y), g4);
                     fma4h(acc, __int_as_float(d2.w), g5); }
    }

    yh[(size_t)r * 32 + lane] = pack4h(acc);
}

// ---------------------------------------------------------------------------
// 6) layer 2 + fused final: out = (feah + learn1h + spmm_h(learn1h)+bias1)/3
//    residual fea read from fp16 shadow; streaming store for out.
// ---------------------------------------------------------------------------
__global__ void __launch_bounds__(256)
spmm2_kernel(const uint2* __restrict__ xh,       // learn1 fp16
             const uint2* __restrict__ feah,     // fea fp16
             float4* __restrict__ out,
             const int* __restrict__ offsets,
             const int4* __restrict__ edges4,
             const float4* __restrict__ bias4,
             int n_nodes) {
    int gtid = blockIdx.x * blockDim.x + threadIdx.x;
    int r = gtid >> 5;
    if (r >= n_nodes) return;
    int lane = threadIdx.x & 31;

    float4 acc = __ldg(bias4 + lane);
    int beg = __ldg(offsets + r);
    int end = __ldg(offsets + r + 1);

    int i = beg;
    for (; i + 8 <= end; i += 8) {
        int4 d0 = __ldg(edges4 + (i >> 1));
        int4 d1 = __ldg(edges4 + (i >> 1) + 1);
        int4 d2 = __ldg(edges4 + (i >> 1) + 2);
        int4 d3 = __ldg(edges4 + (i >> 1) + 3);
        uint2 g0 = __ldg(xh + (size_t)d0.x * 32 + lane);
        uint2 g1 = __ldg(xh + (size_t)d0.z * 32 + lane);
        uint2 g2 = __ldg(xh + (size_t)d1.x * 32 + lane);
        uint2 g3 = __ldg(xh + (size_t)d1.z * 32 + lane);
        uint2 g4 = __ldg(xh + (size_t)d2.x * 32 + lane);
        uint2 g5 = __ldg(xh + (size_t)d2.z * 32 + lane);
        uint2 g6 = __ldg(xh + (size_t)d3.x * 32 + lane);
        uint2 g7 = __ldg(xh + (size_t)d3.z * 32 + lane);
        fma4h(acc, __int_as_float(d0.y), g0);
        fma4h(acc, __int_as_float(d0.w), g1);
        fma4h(acc, __int_as_float(d1.y), g2);
        fma4h(acc, __int_as_float(d1.w), g3);
        fma4h(acc, __int_as_float(d2.y), g4);
        fma4h(acc, __int_as_float(d2.w), g5);
        fma4h(acc, __int_as_float(d3.y), g6);
        fma4h(acc, __int_as_float(d3.w), g7);
    }
    int m = end - i;
    if (m > 0) {
        int4 d0, d1, d2;
        uint2 g0, g1, g2, g3, g4, g5;
        d0 = __ldg(edges4 + (i >> 1));
        if (m > 2) d1 = __ldg(edges4 + (i >> 1) + 1);
        if (m > 4) d2 = __ldg(edges4 + (i >> 1) + 2);
        g0 = __ldg(xh + (size_t)d0.x * 32 + lane);
        g1 = __ldg(xh + (size_t)d0.z * 32 + lane);
        if (m > 2) { g2 = __ldg(xh + (size_t)d1.x * 32 + lane);
                     g3 = __ldg(xh + (size_t)d1.z * 32 + lane); }
        if (m > 4) { g4 = __ldg(xh + (size_t)d2.x * 32 + lane);
                     g5 = __ldg(xh + (size_t)d2.z * 32 + lane); }
        fma4h(acc, __int_as_float(d0.y), g0);
        fma4h(acc, __int_as_float(d0.w), g1);
        if (m > 2) { fma4h(acc, __int_as_float(d1.y), g2);
                     fma4h(acc, __int_as_float(d1.w), g3); }
        if (m > 4) { fma4h(acc, __int_as_float(d2.y), g4);
                     fma4h(acc, __int_as_float(d2.w), g5); }
    }

    size_t idx = (size_t)r * 32 + lane;
    const float inv3 = 1.0f / 3.0f;
    float4 f  = unpack4h(__ldg(feah + idx));   // fp16 residual fea
    float4 l1 = unpack4h(__ldg(xh + idx));     // fp16 residual learn1
    acc.x = (f.x + l1.x + acc.x) * inv3;
    acc.y = (f.y + l1.y + acc.y) * inv3;
    acc.z = (f.z + l1.z + acc.z) * inv3;
    acc.w = (f.w + l1.w + acc.w) * inv3;
    __stcs(out + idx, acc);                    // streaming store
}

extern "C" void kernel_launch(void* const* d_in, const int* in_sizes, int n_in,
                              void* d_out, int out_size) {
    const float* fea     = (const float*)d_in[0];
    const int*   adj_row = (const int*)  d_in[1];
    const int*   adj_col = (const int*)  d_in[2];
    const float* adj_val = (const float*)d_in[3];
    const float* bias    = (const float*)d_in[4];

    int n_edges = in_sizes[1];
    int n_nodes = in_sizes[0] / HIDDEN;
    int total4  = n_nodes * 32;
    int nblocks_scan = (n_nodes + SCAN_CHUNK - 1) / SCAN_CHUNK;   // 196

    uint2* feah;    cudaGetSymbolAddress((void**)&feah,    g_feah);
    uint2* learn1h; cudaGetSymbolAddress((void**)&learn1h, g_learn1h);
    int*   counts;  cudaGetSymbolAddress((void**)&counts,  g_counts);
    int*   offs;    cudaGetSymbolAddress((void**)&offs,    g_offsets);
    int*   rank;    cudaGetSymbolAddress((void**)&rank,    g_rank);
    int*   bsum;    cudaGetSymbolAddress((void**)&bsum,    g_bsum);
    int2*  edges;   cudaGetSymbolAddress((void**)&edges,   g_edges);
    float* out = (float*)d_out;

    const int TPB = 256;

    // 1) fused fp16 convert + histogram/rank (counts==0 invariant at entry)
    {
        int work = max(total4, n_edges);
        convert_hist_kernel<<<(work + TPB - 1) / TPB, TPB>>>(
            (const float4*)fea, feah, adj_row, counts, rank, n_edges, total4);
    }

    // 2) block sums of padded counts (196 blocks)
    scan_bsum_kernel<<<nblocks_scan, SCAN_CHUNK>>>(counts, bsum, n_nodes);

    // 3) offsets scan + pad-edge writes
    scan_offsets_pad_kernel<<<nblocks_scan, SCAN_CHUNK>>>(counts, bsum, offs,
                                                          edges, n_nodes,
                                                          nblocks_scan);

    // 4) permute edges (no atomics)
    permute_kernel<<<(n_edges + TPB - 1) / TPB, TPB>>>(adj_row, adj_col, adj_val,
                                                       rank, offs, edges, n_edges);

    // 5) layer 1 (+ restore counts==0)
    {
        int blocks = (n_nodes * 32 + 255) / 256;
        spmm1_kernel<<<blocks, 256>>>(feah, learn1h, offs, (const int4*)edges,
                                      (const float4*)bias, counts, n_nodes);
    }

    // 6) layer 2 + fused final
    {
        int blocks = (n_nodes * 32 + 255) / 256;
        spmm2_kernel<<<blocks, 256>>>(learn1h, feah, (float4*)out,
                                      offs, (const int4*)edges,
                                      (const float4*)(bias + HIDDEN), n_nodes);
    }
}